// round 7
// baseline (speedup 1.0000x reference)
#include <cuda_runtime.h>
#include <cuda_fp16.h>
#include <cstdint>

#define NB 4
#define C  128
#define Q  4096   // HS*WS = HR*WR
#define S  64
#define WS_ 64
#define HS_ 64

#define PT   128           // p rows per CTA
#define QC   128           // q cols per chunk (= 2 src-image rows)
#define NCH  (Q / QC)      // 32 chunks

// ---------------- device scratch ----------------
__device__ __half g_fr_h[(size_t)NB * Q * C];     // (n,p,c) fp16
__device__ __half g_fs_h[(size_t)NB * Q * C];     // (n,q,c) fp16
// Row events: per (n,p) exactly 128 (2 per sample), sorted by chunk.
// meta = s | y<<6 | x0<<12 | x1<<18 ; w0,w1 fp32 (in-bounds folded).
__device__ uint4    g_events[(size_t)NB * Q * 128];
__device__ uint32_t g_eoff[(size_t)NB * Q * 33];
__device__ float    g_cmmv[(size_t)NB * Q * S];

// ---------------- smem layout (bytes) ----------------
static constexpr int SA    = 0;                         // 32768  A tile
static constexpr int SB0   = 32768;                     // 32768  B buf 0
static constexpr int SB1   = 65536;                     // 32768  B buf 1
static constexpr int SCORR = 98304;                     // 128*130*4 = 66560
static constexpr int SACC  = 164864;                    // 32768  out acc
static constexpr int SEOFF = 197632;                    // 128*33*4 = 16896
static constexpr int SMEM_TOTAL = 214528;

// ---------------- helpers ----------------
__device__ __forceinline__ uint32_t smem_u32(const void* p) {
    uint32_t a;
    asm("{ .reg .u64 t; cvta.to.shared.u64 t, %1; cvt.u32.u64 %0, t; }"
        : "=r"(a) : "l"(p));
    return a;
}
// 256B-row smem swizzle: 16B chunk index XOR (row & 7) -> conflict-free ldmatrix.
__device__ __forceinline__ uint32_t swz(int row, int c16) {
    return (uint32_t)row * 256u + (uint32_t)((c16 ^ (row & 7)) << 4);
}
__device__ __forceinline__ void ldsm4(uint32_t* r, uint32_t addr) {
    asm volatile("ldmatrix.sync.aligned.m8n8.x4.shared.b16 {%0,%1,%2,%3}, [%4];"
                 : "=r"(r[0]), "=r"(r[1]), "=r"(r[2]), "=r"(r[3]) : "r"(addr));
}
__device__ __forceinline__ void mma16816(float* d, const uint32_t* a,
                                         uint32_t b0, uint32_t b1) {
    asm volatile("mma.sync.aligned.m16n8k16.row.col.f32.f16.f16.f32 "
                 "{%0,%1,%2,%3}, {%4,%5,%6,%7}, {%8,%9}, {%0,%1,%2,%3};"
                 : "+f"(d[0]), "+f"(d[1]), "+f"(d[2]), "+f"(d[3])
                 : "r"(a[0]), "r"(a[1]), "r"(a[2]), "r"(a[3]), "r"(b0), "r"(b1));
}
__device__ __forceinline__ void cp16(uint32_t dst, const void* src) {
    asm volatile("cp.async.cg.shared.global [%0], [%1], 16;" :: "r"(dst), "l"(src));
}
__device__ __forceinline__ void cp_commit() {
    asm volatile("cp.async.commit_group;" ::: "memory");
}
__device__ __forceinline__ void cp_wait1() {
    asm volatile("cp.async.wait_group 1;" ::: "memory");
}
__device__ __forceinline__ void cp_wait0() {
    asm volatile("cp.async.wait_group 0;" ::: "memory");
}

// ---------------------------------------------------------------------------
// Prelude:
//   blocks [0,2048)    fr -> fp16 transpose (n,p,c)
//   blocks [2048,4096) fs -> fp16 transpose (n,q,c)
//   blocks [4096,4160) event builder + cmmv (1 thread per (n,p))
__global__ __launch_bounds__(256)
void prelude_kernel(const float* __restrict__ fr,
                    const float* __restrict__ fs,
                    const float* __restrict__ grids,
                    const float* __restrict__ mask) {
    const int bid = blockIdx.x;

    if (bid < 4096) {
        __shared__ float tile[32][33];
        const bool is_fs = bid >= 2048;
        const int  b  = bid & 2047;
        const int  n  = b >> 9;
        const int  r  = b & 511;
        const int  q0 = (r >> 2) * 32;
        const int  c0 = (r & 3) * 32;
        const int  tx = threadIdx.x & 31;
        const int  ty = threadIdx.x >> 5;

        const float* src = is_fs ? fs : fr;
        const float* sp  = src + ((size_t)n * C + c0) * Q + q0;
#pragma unroll
        for (int k = 0; k < 4; ++k)
            tile[ty + k * 8][tx] = sp[(size_t)(ty + k * 8) * Q + tx];
        __syncthreads();

        __half* dst = (is_fs ? g_fs_h : g_fr_h) + ((size_t)n * Q + q0) * C + c0;
#pragma unroll
        for (int k = 0; k < 4; ++k)
            dst[(size_t)(ty + k * 8) * C + tx] = __float2half(tile[tx][ty + k * 8]);
        return;
    }

    // ---- event builder ----
    const int g = (bid - 4096) * 256 + threadIdx.x;   // 0..16383
    const int n = g >> 12;
    const int p = g & 4095;

    uint32_t cnt[NCH];
#pragma unroll
    for (int k = 0; k < NCH; ++k) cnt[k] = 0;

    // pass 1: histogram + cmmv
    for (int s = 0; s < S; ++s) {
        const float gx = grids[(((size_t)n * S + s) * 2 + 0) * Q + p];
        const float gy = grids[(((size_t)n * S + s) * 2 + 1) * Q + p];
        const float mv = mask[((size_t)n * S + s) * Q + p];

        const float ix = gx - 0.5f, iy = gy - 0.5f;
        const float x0 = floorf(ix), y0 = floorf(iy);
        const float wx1 = ix - x0, wy1 = iy - y0;
        const int x0i = (int)x0, y0i = (int)y0;

        const bool bx0 = (x0i >= 0) && (x0i < WS_);
        const bool bx1 = (x0i + 1 >= 0) && (x0i + 1 < WS_);
        const bool by0 = (y0i >= 0) && (y0i < HS_);
        const bool by1 = (y0i + 1 >= 0) && (y0i + 1 < HS_);

        const float w00 = (1.f - wx1) * (1.f - wy1) * ((bx0 && by0) ? 1.f : 0.f);
        const float w10 = wx1 * (1.f - wy1) * ((bx1 && by0) ? 1.f : 0.f);
        const float w01 = (1.f - wx1) * wy1 * ((bx0 && by1) ? 1.f : 0.f);
        const float w11 = wx1 * wy1 * ((bx1 && by1) ? 1.f : 0.f);

        const float msum = w00 + w10 + w01 + w11;
        const float cm = (msum < 0.9999f) ? 0.0f : 1.0f;
        g_cmmv[((size_t)n * Q + p) * S + s] = cm * mv;

        const int yc0 = min(max(y0i, 0), HS_ - 1);
        const int yc1 = min(max(y0i + 1, 0), HS_ - 1);
        cnt[yc0 >> 1]++;
        cnt[yc1 >> 1]++;
    }

    uint32_t off[NCH];
    uint32_t run = 0;
    const size_t eob = ((size_t)n * Q + p) * 33;
#pragma unroll
    for (int k = 0; k < NCH; ++k) {
        off[k] = run;
        g_eoff[eob + k] = run;
        run += cnt[k];
    }
    g_eoff[eob + NCH] = run;   // = 128

    // pass 2: emit events
    uint4* evp = g_events + ((size_t)n * Q + p) * 128;
    for (int s = 0; s < S; ++s) {
        const float gx = grids[(((size_t)n * S + s) * 2 + 0) * Q + p];
        const float gy = grids[(((size_t)n * S + s) * 2 + 1) * Q + p];

        const float ix = gx - 0.5f, iy = gy - 0.5f;
        const float x0 = floorf(ix), y0 = floorf(iy);
        const float wx1 = ix - x0, wy1 = iy - y0;
        const int x0i = (int)x0, y0i = (int)y0;

        const bool bx0 = (x0i >= 0) && (x0i < WS_);
        const bool bx1 = (x0i + 1 >= 0) && (x0i + 1 < WS_);
        const bool by0 = (y0i >= 0) && (y0i < HS_);
        const bool by1 = (y0i + 1 >= 0) && (y0i + 1 < HS_);

        const int xc0 = min(max(x0i, 0), WS_ - 1);
        const int xc1 = min(max(x0i + 1, 0), WS_ - 1);
        const int yc0 = min(max(y0i, 0), HS_ - 1);
        const int yc1 = min(max(y0i + 1, 0), HS_ - 1);

        // event for row y0
        {
            const float w0 = (1.f - wx1) * (1.f - wy1) * ((bx0 && by0) ? 1.f : 0.f);
            const float w1 = wx1 * (1.f - wy1) * ((bx1 && by0) ? 1.f : 0.f);
            const uint32_t meta = (uint32_t)s | ((uint32_t)yc0 << 6)
                                | ((uint32_t)xc0 << 12) | ((uint32_t)xc1 << 18);
            evp[off[yc0 >> 1]++] =
                make_uint4(meta, __float_as_uint(w0), __float_as_uint(w1), 0u);
        }
        // event for row y0+1
        {
            const float w0 = (1.f - wx1) * wy1 * ((bx0 && by1) ? 1.f : 0.f);
            const float w1 = wx1 * wy1 * ((bx1 && by1) ? 1.f : 0.f);
            const uint32_t meta = (uint32_t)s | ((uint32_t)yc1 << 6)
                                | ((uint32_t)xc0 << 12) | ((uint32_t)xc1 << 18);
            evp[off[yc1 >> 1]++] =
                make_uint4(meta, __float_as_uint(w0), __float_as_uint(w1), 0u);
        }
    }
}

// ---------------------------------------------------------------------------
// Fused GEMM + sampling. grid (Q/PT, NB), block 256.
__global__ __launch_bounds__(256)
void corr_fused_kernel(float* __restrict__ out) {
    extern __shared__ char smem[];
    const uint32_t sb = smem_u32(smem);
    float* corr_s = (float*)(smem + SCORR);   // [128][130]
    float* acc_s  = (float*)(smem + SACC);    // [128][64]
    uint32_t* eoff_s = (uint32_t*)(smem + SEOFF);   // [128][33]

    const int tid  = threadIdx.x;
    const int wid  = tid >> 5;
    const int lane = tid & 31;
    const int pb   = blockIdx.x * PT;
    const int n    = blockIdx.y;

    // ---- prologue: A tile load (swizzled), acc zero, eoff stage ----
    const __half* Abase = g_fr_h + ((size_t)n * Q + pb) * C;
#pragma unroll
    for (int i = 0; i < 8; ++i) {
        const int j = tid + i * 256;
        const int row = j >> 4, c16 = j & 15;
        const uint4 v = *(const uint4*)(Abase + (size_t)row * C + c16 * 8);
        *(uint4*)(smem + SA + swz(row, c16)) = v;
    }
    for (int i = tid; i < PT * S; i += 256) acc_s[i] = 0.0f;
    for (int i = tid; i < PT * 33; i += 256)
        eoff_s[i] = __ldg(&g_eoff[((size_t)n * Q + pb) * 33 + i]);

    // prefetch B chunk 0
    const __half* Bbase = g_fs_h + (size_t)n * Q * C;
#pragma unroll
    for (int i = 0; i < 8; ++i) {
        const int j = tid + i * 256;
        const int row = j >> 4, c16 = j & 15;
        cp16(sb + SB0 + swz(row, c16), Bbase + (size_t)row * C + c16 * 8);
    }
    cp_commit();

    // per-warp MMA tiling: 4 m-groups x 2 n-groups
    const int mwarp = (wid >> 1) * 32;
    const int nwarp = (wid & 1) * 64;

    // ldmatrix lane address components
    const int arow0 = mwarp + (lane & 15);            // mi adds 16
    const int ac16k = (lane >> 4);                    // + 2*kk
    const int brow0 = nwarp + ((lane >> 4) << 3) + (lane & 7);  // nbq adds 16
    const int bc16k = ((lane >> 3) & 1);              // + 2*kk

    // sampling partition: warp owns p rows [wid*16, wid*16+16)
    const int prow = wid * 16 + (lane >> 1);
    const int slot = lane & 1;
    const uint4* evp = g_events + ((size_t)n * Q + pb + prow) * 128;

    for (int c = 0; c < NCH; ++c) {
        if (c + 1 < NCH) {
            const uint32_t bdst = ((c + 1) & 1) ? SB1 : SB0;
            const __half* Bsrc = Bbase + (size_t)(c + 1) * QC * C;
#pragma unroll
            for (int i = 0; i < 8; ++i) {
                const int j = tid + i * 256;
                const int row = j >> 4, c16 = j & 15;
                cp16(sb + bdst + swz(row, c16), Bsrc + (size_t)row * C + c16 * 8);
            }
            cp_commit();
            cp_wait1();
        } else {
            cp_wait0();
        }
        __syncthreads();

        // ---- MMA: corr tile [128][128] fp32 ----
        const uint32_t bbuf = sb + ((c & 1) ? SB1 : SB0);
        float acc[2][8][4];
#pragma unroll
        for (int mi = 0; mi < 2; ++mi)
#pragma unroll
            for (int nt = 0; nt < 8; ++nt)
#pragma unroll
                for (int k = 0; k < 4; ++k) acc[mi][nt][k] = 0.0f;

#pragma unroll
        for (int kk = 0; kk < 8; ++kk) {
            uint32_t a[2][4];
#pragma unroll
            for (int mi = 0; mi < 2; ++mi)
                ldsm4(a[mi], sb + SA + swz(arow0 + mi * 16, 2 * kk + ac16k));
            uint32_t b[4][4];
#pragma unroll
            for (int nbq = 0; nbq < 4; ++nbq)
                ldsm4(b[nbq], bbuf + swz(brow0 + nbq * 16, 2 * kk + bc16k));
#pragma unroll
            for (int mi = 0; mi < 2; ++mi)
#pragma unroll
                for (int nt = 0; nt < 8; ++nt)
                    mma16816(acc[mi][nt], a[mi],
                             b[nt >> 1][(nt & 1) * 2], b[nt >> 1][(nt & 1) * 2 + 1]);
        }

        // store corr tile to smem (fp32, stride 130)
        const int crow = lane >> 2;
        const int ccol = (lane & 3) * 2;
#pragma unroll
        for (int mi = 0; mi < 2; ++mi)
#pragma unroll
            for (int nt = 0; nt < 8; ++nt) {
                const int r0 = mwarp + mi * 16 + crow;
                const int cc = nwarp + nt * 8 + ccol;
                *(float2*)&corr_s[(size_t)r0 * 130 + cc] =
                    make_float2(acc[mi][nt][0], acc[mi][nt][1]);
                *(float2*)&corr_s[(size_t)(r0 + 8) * 130 + cc] =
                    make_float2(acc[mi][nt][2], acc[mi][nt][3]);
            }
        __syncthreads();

        // ---- sampling: scatter events of this chunk into acc ----
        const uint32_t e0 = eoff_s[prow * 33 + c];
        const uint32_t e1 = eoff_s[prow * 33 + c + 1];
        for (uint32_t j = e0 + slot; j < e1; j += 2) {
            const uint4 ev = __ldg(&evp[j]);
            const int s  = ev.x & 63;
            const int y  = (ev.x >> 6) & 63;
            const int x0 = (ev.x >> 12) & 63;
            const int x1 = (ev.x >> 18) & 63;
            const int rb = (y & 1) * 64;
            const float v = __uint_as_float(ev.y) * corr_s[(size_t)prow * 130 + rb + x0]
                          + __uint_as_float(ev.z) * corr_s[(size_t)prow * 130 + rb + x1];
            atomicAdd(&acc_s[prow * S + s], v);
        }
        __syncthreads();
    }

    // ---- epilogue: out (n,s,p) and corr_mask (n,s,p) ----
    float* outp = out + (size_t)n * S * Q + pb;
    float* cmp  = outp + (size_t)NB * S * Q;
    for (int i = tid; i < PT * S; i += 256) {
        const int s = i >> 7;          // 0..63
        const int p = i & 127;         // 0..127
        const float cm = __ldg(&g_cmmv[((size_t)n * Q + pb + p) * S + s]);
        outp[(size_t)s * Q + p] = acc_s[p * S + s] * cm;
        cmp[(size_t)s * Q + p]  = cm;
    }
}

// ---------------------------------------------------------------------------
extern "C" void kernel_launch(void* const* d_in, const int* in_sizes, int n_in,
                              void* d_out, int out_size) {
    const float* fr    = (const float*)d_in[0];
    const float* fs    = (const float*)d_in[1];
    const float* grids = (const float*)d_in[2];
    const float* mask  = (const float*)d_in[3];
    float* out = (float*)d_out;

    cudaFuncSetAttribute(corr_fused_kernel,
                         cudaFuncAttributeMaxDynamicSharedMemorySize, SMEM_TOTAL);

    prelude_kernel<<<4160, 256>>>(fr, fs, grids, mask);
    corr_fused_kernel<<<dim3(Q / PT, NB), 256, SMEM_TOTAL>>>(out);
}

// round 8
// speedup vs baseline: 3.7864x; 3.7864x over previous
#include <cuda_runtime.h>
#include <cuda_fp16.h>
#include <cstdint>

#define NB 4
#define C  128
#define Q  4096   // HS*WS = HR*WR
#define S  64
#define WS_ 64
#define HS_ 64

#define PT   128           // p rows per CTA
#define QC   128           // q cols per chunk (= 2 src-image rows)
#define NCH  (Q / QC)      // 32 chunks

// ---------------- device scratch ----------------
__device__ __half g_fr_h[(size_t)NB * Q * C];     // (n,p,c) fp16
__device__ __half g_fs_h[(size_t)NB * Q * C];     // (n,q,c) fp16
// One event per sample, sorted by trigger chunk t = yc1>>1.
// meta = s | r1<<6 | r0sel<<7 | x0<<9 | x1<<15
// w = (wa0, wa1, wb0, wb1) * cm * mv   (row yc0 weights, row yc1 weights)
__device__ uint32_t g_emeta[(size_t)NB * Q * S];
__device__ float4   g_ew[(size_t)NB * Q * S];
__device__ uint32_t g_eoff[(size_t)NB * Q * 33];

// ---------------- smem layout (bytes) ----------------
static constexpr int SA    = 0;         // 32768  A tile (swizzled fp16)
static constexpr int SB0   = 32768;     // 32768  B buf 0
static constexpr int SB1   = 65536;     // 32768  B buf 1
static constexpr int SCB0  = 98304;     // corr buf 0: 128 p x 2 rows x 72 halves
static constexpr int CBUF  = 128 * 144 * 2;   // 36864
static constexpr int SP0   = SCB0 + 2 * CBUF; // 172032: prev-row bufs
static constexpr int PBUF  = 128 * 72 * 2;    // 18432
static constexpr int SMEM_TOTAL = SP0 + 2 * PBUF;   // 208896

// ---------------- helpers ----------------
__device__ __forceinline__ uint32_t smem_u32(const void* p) {
    uint32_t a;
    asm("{ .reg .u64 t; cvta.to.shared.u64 t, %1; cvt.u32.u64 %0, t; }"
        : "=r"(a) : "l"(p));
    return a;
}
// 256B-row smem swizzle for 16B chunks (conflict-free ldmatrix).
__device__ __forceinline__ uint32_t swz(int row, int c16) {
    return (uint32_t)row * 256u + (uint32_t)((c16 ^ (row & 7)) << 4);
}
__device__ __forceinline__ void ldsm4(uint32_t* r, uint32_t addr) {
    asm volatile("ldmatrix.sync.aligned.m8n8.x4.shared.b16 {%0,%1,%2,%3}, [%4];"
                 : "=r"(r[0]), "=r"(r[1]), "=r"(r[2]), "=r"(r[3]) : "r"(addr));
}
__device__ __forceinline__ void mma16816(float* d, const uint32_t* a,
                                         uint32_t b0, uint32_t b1) {
    asm volatile("mma.sync.aligned.m16n8k16.row.col.f32.f16.f16.f32 "
                 "{%0,%1,%2,%3}, {%4,%5,%6,%7}, {%8,%9}, {%0,%1,%2,%3};"
                 : "+f"(d[0]), "+f"(d[1]), "+f"(d[2]), "+f"(d[3])
                 : "r"(a[0]), "r"(a[1]), "r"(a[2]), "r"(a[3]), "r"(b0), "r"(b1));
}
__device__ __forceinline__ void cp16(uint32_t dst, const void* src) {
    asm volatile("cp.async.cg.shared.global [%0], [%1], 16;" :: "r"(dst), "l"(src));
}
__device__ __forceinline__ void cp_commit() {
    asm volatile("cp.async.commit_group;" ::: "memory");
}
__device__ __forceinline__ void cp_wait0() {
    asm volatile("cp.async.wait_group 0;" ::: "memory");
}

// ---------------------------------------------------------------------------
// Prelude:
//   blocks [0,2048)     fr -> fp16 transpose (n,p,c)
//   blocks [2048,4096)  fs -> fp16 transpose (n,q,c)
//   blocks [4096,6144)  event builder (warp per (n,p)) + corr_mask output
__global__ __launch_bounds__(256)
void prelude_kernel(const float* __restrict__ fr,
                    const float* __restrict__ fs,
                    const float* __restrict__ grids,
                    const float* __restrict__ mask,
                    float* __restrict__ out) {
    const int bid = blockIdx.x;
    const int tid = threadIdx.x;

    if (bid < 4096) {
        __shared__ float tile[32][33];
        const bool is_fs = bid >= 2048;
        const int  b  = bid & 2047;
        const int  n  = b >> 9;
        const int  r  = b & 511;
        const int  q0 = (r >> 2) * 32;
        const int  c0 = (r & 3) * 32;
        const int  tx = tid & 31;
        const int  ty = tid >> 5;

        const float* src = is_fs ? fs : fr;
        const float* sp  = src + ((size_t)n * C + c0) * Q + q0;
#pragma unroll
        for (int k = 0; k < 4; ++k)
            tile[ty + k * 8][tx] = sp[(size_t)(ty + k * 8) * Q + tx];
        __syncthreads();

        __half* dst = (is_fs ? g_fs_h : g_fr_h) + ((size_t)n * Q + q0) * C + c0;
#pragma unroll
        for (int k = 0; k < 4; ++k)
            dst[(size_t)(ty + k * 8) * C + tx] = __float2half(tile[tx][ty + k * 8]);
        return;
    }

    // ---- event builder: warp wid handles p = p0 + wid ----
    __shared__ float    s_g[S][2][8];
    __shared__ float    s_m[S][8];
    __shared__ uint32_t s_off[8][32];

    const int b   = bid - 4096;            // 0..2047
    const int n   = b >> 9;
    const int p0  = (b & 511) * 8;
    const int wid = tid >> 5;
    const int lane = tid & 31;
    const int p   = p0 + wid;

    for (int i = tid; i < S * 2 * 8; i += 256) {
        const int s = i >> 4, xy = (i >> 3) & 1, j = i & 7;
        s_g[s][xy][j] = grids[(((size_t)n * S + s) * 2 + xy) * Q + p0 + j];
    }
    for (int i = tid; i < S * 8; i += 256) {
        const int s = i >> 3, j = i & 7;
        s_m[s][j] = mask[((size_t)n * S + s) * Q + p0 + j];
    }
    s_off[wid][lane] = 0;
    __syncthreads();

    uint32_t ev_meta[2];
    float4   ev_w[2];
    int      ev_t[2];
    float*   cmask = out + (size_t)NB * S * Q + (size_t)n * S * Q + p;

#pragma unroll
    for (int k = 0; k < 2; ++k) {
        const int s = lane + k * 32;
        const float gx = s_g[s][0][wid];
        const float gy = s_g[s][1][wid];
        const float mv = s_m[s][wid];

        const float ix = gx - 0.5f, iy = gy - 0.5f;
        const float x0f = floorf(ix), y0f = floorf(iy);
        const float wx1 = ix - x0f, wy1 = iy - y0f;
        const int x0i = (int)x0f, y0i = (int)y0f;

        const bool bx0 = (x0i >= 0) && (x0i < WS_);
        const bool bx1 = (x0i + 1 < WS_);        // x0i+1 >= 0 always when relevant
        const bool by0 = (y0i >= 0) && (y0i < HS_);
        const bool by1 = (y0i + 1 >= 0) && (y0i + 1 < HS_);

        float wa0 = (1.f - wx1) * (1.f - wy1) * ((bx0 && by0) ? 1.f : 0.f);
        float wa1 = wx1 * (1.f - wy1) * ((bx1 && (x0i + 1 >= 0) && by0) ? 1.f : 0.f);
        float wb0 = (1.f - wx1) * wy1 * ((bx0 && by1) ? 1.f : 0.f);
        float wb1 = wx1 * wy1 * ((bx1 && (x0i + 1 >= 0) && by1) ? 1.f : 0.f);

        const float msum = wa0 + wa1 + wb0 + wb1;
        const float cm = (msum < 0.9999f) ? 0.0f : 1.0f;
        const float f  = cm * mv;
        cmask[(size_t)s * Q] = f;

        const int xc0 = min(max(x0i, 0), WS_ - 1);
        const int xc1 = min(max(x0i + 1, 0), WS_ - 1);
        const int yc0 = min(max(y0i, 0), HS_ - 1);
        const int yc1 = min(max(y0i + 1, 0), HS_ - 1);

        const int t  = yc1 >> 1;
        const int r1 = yc1 & 1;
        const int r0sel = ((yc0 >> 1) == t) ? (yc0 & 1) : 2;

        ev_meta[k] = (uint32_t)s | ((uint32_t)r1 << 6) | ((uint32_t)r0sel << 7)
                   | ((uint32_t)xc0 << 9) | ((uint32_t)xc1 << 15);
        ev_w[k] = make_float4(wa0 * f, wa1 * f, wb0 * f, wb1 * f);
        ev_t[k] = t;
        atomicAdd(&s_off[wid][t], 1);
    }
    __syncwarp();

    // exclusive scan of counts over 32 chunks
    const uint32_t v = s_off[wid][lane];
    uint32_t x = v;
#pragma unroll
    for (int o = 1; o < 32; o <<= 1) {
        const uint32_t y = __shfl_up_sync(0xFFFFFFFFu, x, o);
        if (lane >= o) x += y;
    }
    const uint32_t excl = x - v;
    const size_t eob = ((size_t)n * Q + p) * 33;
    g_eoff[eob + lane] = excl;
    if (lane == 31) g_eoff[eob + 32] = x;   // = 64
    __syncwarp();
    s_off[wid][lane] = excl;
    __syncwarp();

    const size_t evb = ((size_t)n * Q + p) * S;
#pragma unroll
    for (int k = 0; k < 2; ++k) {
        const uint32_t pos = atomicAdd(&s_off[wid][ev_t[k]], 1);
        g_emeta[evb + pos] = ev_meta[k];
        g_ew[evb + pos]    = ev_w[k];
    }
}

// ---------------------------------------------------------------------------
// Fused warp-specialized GEMM + sampling. grid (Q/PT, NB), block 512.
// Warps 0-7: MMA producer (corr chunk c -> fp16 cbuf[c&1]).
// Warps 8-15: B prefetch (cp.async) + sample trigger c-1 + prev-row copy.
__global__ __launch_bounds__(512, 1)
void corr_fused_kernel(float* __restrict__ out) {
    extern __shared__ char smem[];
    const uint32_t sb = smem_u32(smem);

    const int tid  = threadIdx.x;
    const int wid  = tid >> 5;
    const int lane = tid & 31;
    const int pb   = blockIdx.x * PT;
    const int n    = blockIdx.y;

    // ---- prologue: A tile (all threads), B0 (samplers) ----
    const __half* Abase = g_fr_h + ((size_t)n * Q + pb) * C;
#pragma unroll
    for (int i = 0; i < 4; ++i) {
        const int j = tid + i * 512;
        const int row = j >> 4, c16 = j & 15;
        const uint4 vv = *(const uint4*)(Abase + (size_t)row * C + c16 * 8);
        *(uint4*)(smem + SA + swz(row, c16)) = vv;
    }
    const __half* Bbase = g_fs_h + (size_t)n * Q * C;
    if (tid >= 256) {
        const int sampid = tid - 256;
#pragma unroll
        for (int i = 0; i < 8; ++i) {
            const int j = sampid + i * 256;
            const int row = j >> 4, c16 = j & 15;
            cp16(sb + SB0 + swz(row, c16), Bbase + (size_t)row * C + c16 * 8);
        }
        cp_commit();
        cp_wait0();
    }
    __syncthreads();

    // MMA warp constants (warps 0-7): 4 m-groups x 2 n-groups
    const int mwarp = (wid >> 1) * 32;
    const int nwarp = (wid & 1) * 64;
    const int arow0 = mwarp + (lane & 15);
    const int ac16k = (lane >> 4);
    const int brow0 = nwarp + ((lane >> 4) << 3) + (lane & 7);
    const int bc16k = ((lane >> 3) & 1);

    for (int c = 0; c <= NCH; ++c) {
        if (tid >= 256) {
            const int sampid = tid - 256;
            // prefetch B(c+1)
            if (c + 1 < NCH) {
                const uint32_t bdst = ((c + 1) & 1) ? SB1 : SB0;
                const __half* Bsrc = Bbase + (size_t)(c + 1) * QC * C;
#pragma unroll
                for (int i = 0; i < 8; ++i) {
                    const int j = sampid + i * 256;
                    const int row = j >> 4, c16 = j & 15;
                    cp16(sb + bdst + swz(row, c16), Bsrc + (size_t)row * C + c16 * 8);
                }
                cp_commit();
            }
            if (c >= 1) {
                const int t = c - 1;
                const __half* cbT = (const __half*)(smem + SCB0 + (size_t)(t & 1) * CBUF);
                const __half* Pr  = (const __half*)(smem + SP0 + (size_t)((t + 1) & 1) * PBUF);
                __half*       Pw  = (__half*)(smem + SP0 + (size_t)(t & 1) * PBUF);

                const int prow = sampid >> 1;
                const int slot = sampid & 1;
                const size_t pbase = (size_t)n * Q + pb + prow;
                const uint32_t e0 = __ldg(&g_eoff[pbase * 33 + t]);
                const uint32_t e1 = __ldg(&g_eoff[pbase * 33 + t + 1]);
                const uint32_t* mp = g_emeta + pbase * S;
                const float4*   wp = g_ew + pbase * S;
                const __half*   cbp = cbT + (size_t)prow * 144;
                float* outb = out + (size_t)n * S * Q + pb + prow;

                for (uint32_t j = e0 + slot; j < e1; j += 2) {
                    const uint32_t m = __ldg(&mp[j]);
                    const float4  w = __ldg(&wp[j]);
                    const int s   = m & 63;
                    const int r1  = (m >> 6) & 1;
                    const int r0s = (m >> 7) & 3;
                    const int x0  = (m >> 9) & 63;
                    const int x1  = (m >> 15) & 63;
                    const __half* rb = cbp + r1 * 72;
                    const __half* ra = (r0s == 2) ? (Pr + (size_t)prow * 72)
                                                  : (cbp + r0s * 72);
                    const float vv = w.x * __half2float(ra[x0])
                                   + w.y * __half2float(ra[x1])
                                   + w.z * __half2float(rb[x0])
                                   + w.w * __half2float(rb[x1]);
                    outb[(size_t)s * Q] = vv;
                }
                // save row 2t+1 for trigger t+1
#pragma unroll
                for (int k2 = 0; k2 < 16; ++k2) {
                    const int idx = sampid + k2 * 256;
                    const int pp = idx >> 5;
                    const int oo = (idx & 31) * 2;
                    *(__half2*)(Pw + (size_t)pp * 72 + oo) =
                        *(const __half2*)(cbT + (size_t)pp * 144 + 72 + oo);
                }
            }
            cp_wait0();
        } else if (c < NCH) {
            // ---- MMA: corr chunk c -> cbuf[c&1] (fp16) ----
            const uint32_t bbuf = sb + ((c & 1) ? SB1 : SB0);
            float acc[2][8][4];
#pragma unroll
            for (int mi = 0; mi < 2; ++mi)
#pragma unroll
                for (int nt = 0; nt < 8; ++nt)
#pragma unroll
                    for (int k = 0; k < 4; ++k) acc[mi][nt][k] = 0.0f;

#pragma unroll
            for (int kk = 0; kk < 8; ++kk) {
                uint32_t a[2][4];
#pragma unroll
                for (int mi = 0; mi < 2; ++mi)
                    ldsm4(a[mi], sb + SA + swz(arow0 + mi * 16, 2 * kk + ac16k));
                uint32_t b4[4][4];
#pragma unroll
                for (int nbq = 0; nbq < 4; ++nbq)
                    ldsm4(b4[nbq], bbuf + swz(brow0 + nbq * 16, 2 * kk + bc16k));
#pragma unroll
                for (int mi = 0; mi < 2; ++mi)
#pragma unroll
                    for (int nt = 0; nt < 8; ++nt)
                        mma16816(acc[mi][nt], a[mi],
                                 b4[nt >> 1][(nt & 1) * 2], b4[nt >> 1][(nt & 1) * 2 + 1]);
            }

            __half* cb = (__half*)(smem + SCB0 + (size_t)(c & 1) * CBUF);
            const int crow = lane >> 2;
            const int cc2  = (lane & 3) * 2;
#pragma unroll
            for (int mi = 0; mi < 2; ++mi)
#pragma unroll
                for (int nt = 0; nt < 8; ++nt) {
                    const int r0 = mwarp + mi * 16 + crow;
                    const int cc = nwarp + nt * 8 + cc2;
                    const int rowin = cc >> 6, xx = cc & 63;
                    *(__half2*)(cb + (size_t)r0 * 144 + rowin * 72 + xx) =
                        __floats2half2_rn(acc[mi][nt][0], acc[mi][nt][1]);
                    *(__half2*)(cb + (size_t)(r0 + 8) * 144 + rowin * 72 + xx) =
                        __floats2half2_rn(acc[mi][nt][2], acc[mi][nt][3]);
                }
        }
        __syncthreads();
    }
}

// ---------------------------------------------------------------------------
extern "C" void kernel_launch(void* const* d_in, const int* in_sizes, int n_in,
                              void* d_out, int out_size) {
    const float* fr    = (const float*)d_in[0];
    const float* fs    = (const float*)d_in[1];
    const float* grids = (const float*)d_in[2];
    const float* mask  = (const float*)d_in[3];
    float* out = (float*)d_out;

    cudaFuncSetAttribute(corr_fused_kernel,
                         cudaFuncAttributeMaxDynamicSharedMemorySize, SMEM_TOTAL);

    prelude_kernel<<<6144, 256>>>(fr, fs, grids, mask, out);
    corr_fused_kernel<<<dim3(Q / PT, NB), 512, SMEM_TOTAL>>>(out);
}

// round 9
// speedup vs baseline: 4.1450x; 1.0947x over previous
#include <cuda_runtime.h>
#include <cuda_fp16.h>
#include <cstdint>

#define NB 4
#define C  128
#define Q  4096   // HS*WS = HR*WR
#define S  64
#define WS_ 64
#define HS_ 64

#define PT   128           // p rows per CTA
#define QC   128           // q cols per chunk (= 2 src-image rows)
#define NCH  (Q / QC)      // 32 chunks

// ---------------- device scratch ----------------
__device__ __half g_fr_h[(size_t)NB * Q * C];     // (n,p,c) fp16
__device__ __half g_fs_h[(size_t)NB * Q * C];     // (n,q,c) fp16
// One event per sample, sorted by trigger chunk t = yc1>>1.
// meta = s | r1<<6 | r0sel<<7 | x0<<9 | x1<<15
// w = (wa0, wa1, wb0, wb1) * cm * mv   (row yc0 weights, row yc1 weights)
__device__ uint32_t g_emeta[(size_t)NB * Q * S];
__device__ float4   g_ew[(size_t)NB * Q * S];
__device__ uint32_t g_eoff[(size_t)NB * Q * 33];

// ---------------- smem layout (bytes) ----------------
static constexpr int SA    = 0;                    // 32768  A tile (swizzled fp16)
static constexpr int SB    = 32768;                // 3 x 32768 B ring
static constexpr int SCE   = SB + 3 * 32768;       // 131072: even-row corr ring [2]
static constexpr int RBUF  = 128 * 72 * 2;         // 18432 per row buffer
static constexpr int SCO   = SCE + 2 * RBUF;       // 167936: odd-row corr ring [3]
static constexpr int SMEM_TOTAL = SCO + 3 * RBUF;  // 223232

// ---------------- helpers ----------------
__device__ __forceinline__ uint32_t smem_u32(const void* p) {
    uint32_t a;
    asm("{ .reg .u64 t; cvta.to.shared.u64 t, %1; cvt.u32.u64 %0, t; }"
        : "=r"(a) : "l"(p));
    return a;
}
// 256B-row smem swizzle for 16B chunks (conflict-free ldmatrix).
__device__ __forceinline__ uint32_t swz(int row, int c16) {
    return (uint32_t)row * 256u + (uint32_t)((c16 ^ (row & 7)) << 4);
}
__device__ __forceinline__ void ldsm4(uint32_t* r, uint32_t addr) {
    asm volatile("ldmatrix.sync.aligned.m8n8.x4.shared.b16 {%0,%1,%2,%3}, [%4];"
                 : "=r"(r[0]), "=r"(r[1]), "=r"(r[2]), "=r"(r[3]) : "r"(addr));
}
__device__ __forceinline__ void mma16816(float* d, const uint32_t* a,
                                         uint32_t b0, uint32_t b1) {
    asm volatile("mma.sync.aligned.m16n8k16.row.col.f32.f16.f16.f32 "
                 "{%0,%1,%2,%3}, {%4,%5,%6,%7}, {%8,%9}, {%0,%1,%2,%3};"
                 : "+f"(d[0]), "+f"(d[1]), "+f"(d[2]), "+f"(d[3])
                 : "r"(a[0]), "r"(a[1]), "r"(a[2]), "r"(a[3]), "r"(b0), "r"(b1));
}
__device__ __forceinline__ void cp16(uint32_t dst, const void* src) {
    asm volatile("cp.async.cg.shared.global [%0], [%1], 16;" :: "r"(dst), "l"(src));
}
__device__ __forceinline__ void cp_commit() {
    asm volatile("cp.async.commit_group;" ::: "memory");
}
__device__ __forceinline__ void cp_wait1() {
    asm volatile("cp.async.wait_group 1;" ::: "memory");
}
__device__ __forceinline__ void cp_wait0() {
    asm volatile("cp.async.wait_group 0;" ::: "memory");
}

// ---------------------------------------------------------------------------
// Prelude:
//   blocks [0,2048)     fr -> fp16 transpose (n,p,c)
//   blocks [2048,4096)  fs -> fp16 transpose (n,q,c)
//   blocks [4096,6144)  event builder (warp per (n,p)) + corr_mask output
__global__ __launch_bounds__(256)
void prelude_kernel(const float* __restrict__ fr,
                    const float* __restrict__ fs,
                    const float* __restrict__ grids,
                    const float* __restrict__ mask,
                    float* __restrict__ out) {
    const int bid = blockIdx.x;
    const int tid = threadIdx.x;

    if (bid < 4096) {
        __shared__ float tile[32][33];
        const bool is_fs = bid >= 2048;
        const int  b  = bid & 2047;
        const int  n  = b >> 9;
        const int  r  = b & 511;
        const int  q0 = (r >> 2) * 32;
        const int  c0 = (r & 3) * 32;
        const int  tx = tid & 31;
        const int  ty = tid >> 5;

        const float* src = is_fs ? fs : fr;
        const float* sp  = src + ((size_t)n * C + c0) * Q + q0;
#pragma unroll
        for (int k = 0; k < 4; ++k)
            tile[ty + k * 8][tx] = sp[(size_t)(ty + k * 8) * Q + tx];
        __syncthreads();

        __half* dst = (is_fs ? g_fs_h : g_fr_h) + ((size_t)n * Q + q0) * C + c0;
#pragma unroll
        for (int k = 0; k < 4; ++k)
            dst[(size_t)(ty + k * 8) * C + tx] = __float2half(tile[tx][ty + k * 8]);
        return;
    }

    // ---- event builder: warp wid handles p = p0 + wid ----
    __shared__ float    s_g[S][2][8];
    __shared__ float    s_m[S][8];
    __shared__ uint32_t s_off[8][32];

    const int b   = bid - 4096;            // 0..2047
    const int n   = b >> 9;
    const int p0  = (b & 511) * 8;
    const int wid = tid >> 5;
    const int lane = tid & 31;
    const int p   = p0 + wid;

    for (int i = tid; i < S * 2 * 8; i += 256) {
        const int s = i >> 4, xy = (i >> 3) & 1, j = i & 7;
        s_g[s][xy][j] = grids[(((size_t)n * S + s) * 2 + xy) * Q + p0 + j];
    }
    for (int i = tid; i < S * 8; i += 256) {
        const int s = i >> 3, j = i & 7;
        s_m[s][j] = mask[((size_t)n * S + s) * Q + p0 + j];
    }
    s_off[wid][lane] = 0;
    __syncthreads();

    uint32_t ev_meta[2];
    float4   ev_w[2];
    int      ev_t[2];
    float*   cmask = out + (size_t)NB * S * Q + (size_t)n * S * Q + p;

#pragma unroll
    for (int k = 0; k < 2; ++k) {
        const int s = lane + k * 32;
        const float gx = s_g[s][0][wid];
        const float gy = s_g[s][1][wid];
        const float mv = s_m[s][wid];

        const float ix = gx - 0.5f, iy = gy - 0.5f;
        const float x0f = floorf(ix), y0f = floorf(iy);
        const float wx1 = ix - x0f, wy1 = iy - y0f;
        const int x0i = (int)x0f, y0i = (int)y0f;

        const bool bx0 = (x0i >= 0) && (x0i < WS_);
        const bool bx1 = (x0i + 1 >= 0) && (x0i + 1 < WS_);
        const bool by0 = (y0i >= 0) && (y0i < HS_);
        const bool by1 = (y0i + 1 >= 0) && (y0i + 1 < HS_);

        float wa0 = (1.f - wx1) * (1.f - wy1) * ((bx0 && by0) ? 1.f : 0.f);
        float wa1 = wx1 * (1.f - wy1) * ((bx1 && by0) ? 1.f : 0.f);
        float wb0 = (1.f - wx1) * wy1 * ((bx0 && by1) ? 1.f : 0.f);
        float wb1 = wx1 * wy1 * ((bx1 && by1) ? 1.f : 0.f);

        const float msum = wa0 + wa1 + wb0 + wb1;
        const float cm = (msum < 0.9999f) ? 0.0f : 1.0f;
        const float f  = cm * mv;
        cmask[(size_t)s * Q] = f;

        const int xc0 = min(max(x0i, 0), WS_ - 1);
        const int xc1 = min(max(x0i + 1, 0), WS_ - 1);
        const int yc0 = min(max(y0i, 0), HS_ - 1);
        const int yc1 = min(max(y0i + 1, 0), HS_ - 1);

        const int t  = yc1 >> 1;
        const int r1 = yc1 & 1;
        const int r0sel = ((yc0 >> 1) == t) ? (yc0 & 1) : 2;

        ev_meta[k] = (uint32_t)s | ((uint32_t)r1 << 6) | ((uint32_t)r0sel << 7)
                   | ((uint32_t)xc0 << 9) | ((uint32_t)xc1 << 15);
        ev_w[k] = make_float4(wa0 * f, wa1 * f, wb0 * f, wb1 * f);
        ev_t[k] = t;
        atomicAdd(&s_off[wid][t], 1);
    }
    __syncwarp();

    // exclusive scan of counts over 32 chunks
    const uint32_t v = s_off[wid][lane];
    uint32_t x = v;
#pragma unroll
    for (int o = 1; o < 32; o <<= 1) {
        const uint32_t y = __shfl_up_sync(0xFFFFFFFFu, x, o);
        if (lane >= o) x += y;
    }
    const uint32_t excl = x - v;
    const size_t eob = ((size_t)n * Q + p) * 33;
    g_eoff[eob + lane] = excl;
    if (lane == 31) g_eoff[eob + 32] = x;   // = 64
    __syncwarp();
    s_off[wid][lane] = excl;
    __syncwarp();

    const size_t evb = ((size_t)n * Q + p) * S;
#pragma unroll
    for (int k = 0; k < 2; ++k) {
        const uint32_t pos = atomicAdd(&s_off[wid][ev_t[k]], 1);
        g_emeta[evb + pos] = ev_meta[k];
        g_ew[evb + pos]    = ev_w[k];
    }
}

// ---------------------------------------------------------------------------
// Fused warp-specialized GEMM + sampling. grid (Q/PT, NB), block 512.
// Warps 0-7: MMA producer -> even-row ring [2] / odd-row ring [3].
// Warps 8-15: B prefetch (triple-buffered cp.async) + sample trigger c-1.
__global__ __launch_bounds__(512, 1)
void corr_fused_kernel(float* __restrict__ out) {
    extern __shared__ char smem[];
    const uint32_t sb = smem_u32(smem);

    const int tid  = threadIdx.x;
    const int wid  = tid >> 5;
    const int lane = tid & 31;
    const int pb   = blockIdx.x * PT;
    const int n    = blockIdx.y;

    // ---- prologue: A tile (all threads), B0+B1 prefetch (samplers) ----
    const __half* Abase = g_fr_h + ((size_t)n * Q + pb) * C;
#pragma unroll
    for (int i = 0; i < 4; ++i) {
        const int j = tid + i * 512;
        const int row = j >> 4, c16 = j & 15;
        const uint4 vv = *(const uint4*)(Abase + (size_t)row * C + c16 * 8);
        *(uint4*)(smem + SA + swz(row, c16)) = vv;
    }
    const __half* Bbase = g_fs_h + (size_t)n * Q * C;
    if (tid >= 256) {
        const int sampid = tid - 256;
#pragma unroll
        for (int k = 0; k < 2; ++k) {
            const __half* Bsrc = Bbase + (size_t)k * QC * C;
#pragma unroll
            for (int i = 0; i < 8; ++i) {
                const int j = sampid + i * 256;
                const int row = j >> 4, c16 = j & 15;
                cp16(sb + SB + k * 32768 + swz(row, c16),
                     Bsrc + (size_t)row * C + c16 * 8);
            }
            cp_commit();
        }
        cp_wait1();   // B0 complete; B1 in flight with a full chunk of slack
    }
    __syncthreads();

    // MMA warp constants (warps 0-7): 4 m-groups x 2 n-groups.
    // nwarp=0 -> even source row (2c); nwarp=64 -> odd source row (2c+1).
    const int mwarp = (wid >> 1) * 32;
    const int nwarp = (wid & 1) * 64;
    const int arow0 = mwarp + (lane & 15);
    const int ac16k = (lane >> 4);
    const int brow0 = nwarp + ((lane >> 4) << 3) + (lane & 7);
    const int bc16k = ((lane >> 3) & 1);

    for (int c = 0; c <= NCH; ++c) {
        if (tid >= 256) {
            const int sampid = tid - 256;
            // prefetch B(c+2) into ring slot (c+2)%3
            if (c + 2 < NCH) {
                const uint32_t bdst = sb + SB + ((c + 2) % 3) * 32768;
                const __half* Bsrc = Bbase + (size_t)(c + 2) * QC * C;
#pragma unroll
                for (int i = 0; i < 8; ++i) {
                    const int j = sampid + i * 256;
                    const int row = j >> 4, c16 = j & 15;
                    cp16(bdst + swz(row, c16), Bsrc + (size_t)row * C + c16 * 8);
                }
                cp_commit();
            }
            // sample trigger t = c-1 from corr rings
            if (c >= 1) {
                const int t = c - 1;
                const __half* ce = (const __half*)(smem + SCE + (size_t)(t & 1) * RBUF);
                const __half* co = (const __half*)(smem + SCO + (size_t)(t % 3) * RBUF);
                const __half* cp = (const __half*)(smem + SCO + (size_t)((t + 2) % 3) * RBUF);

                const int prow = sampid >> 1;
                const int slot = sampid & 1;
                const size_t pbase = (size_t)n * Q + pb + prow;
                const uint32_t e0 = __ldg(&g_eoff[pbase * 33 + t]);
                const uint32_t e1 = __ldg(&g_eoff[pbase * 33 + t + 1]);
                const uint32_t* mp = g_emeta + pbase * S;
                const float4*   wp = g_ew + pbase * S;
                const size_t roff = (size_t)prow * 72;
                float* outb = out + (size_t)n * S * Q + pb + prow;

                for (uint32_t j = e0 + slot; j < e1; j += 2) {
                    const uint32_t m = __ldg(&mp[j]);
                    const float4  w = __ldg(&wp[j]);
                    const int s   = m & 63;
                    const int r1  = (m >> 6) & 1;
                    const int r0s = (m >> 7) & 3;
                    const int x0  = (m >> 9) & 63;
                    const int x1  = (m >> 15) & 63;
                    const __half* rb = (r1 ? co : ce) + roff;
                    const __half* ra = ((r0s == 2) ? cp : (r0s ? co : ce)) + roff;
                    const float vv = w.x * __half2float(ra[x0])
                                   + w.y * __half2float(ra[x1])
                                   + w.z * __half2float(rb[x0])
                                   + w.w * __half2float(rb[x1]);
                    outb[(size_t)s * Q] = vv;
                }
            }
            // ensure B(c+1) landed before the barrier releases chunk c+1
            if (c + 2 < NCH) cp_wait1();
            else             cp_wait0();
        } else if (c < NCH) {
            // ---- MMA: corr chunk c (rows 2c, 2c+1) ----
            const uint32_t bbuf = sb + SB + (c % 3) * 32768;
            float acc[2][8][4];
#pragma unroll
            for (int mi = 0; mi < 2; ++mi)
#pragma unroll
                for (int nt = 0; nt < 8; ++nt)
#pragma unroll
                    for (int k = 0; k < 4; ++k) acc[mi][nt][k] = 0.0f;

#pragma unroll
            for (int kk = 0; kk < 8; ++kk) {
                uint32_t a[2][4];
#pragma unroll
                for (int mi = 0; mi < 2; ++mi)
                    ldsm4(a[mi], sb + SA + swz(arow0 + mi * 16, 2 * kk + ac16k));
                uint32_t b4[4][4];
#pragma unroll
                for (int nbq = 0; nbq < 4; ++nbq)
                    ldsm4(b4[nbq], bbuf + swz(brow0 + nbq * 16, 2 * kk + bc16k));
#pragma unroll
                for (int mi = 0; mi < 2; ++mi)
#pragma unroll
                    for (int nt = 0; nt < 8; ++nt)
                        mma16816(acc[mi][nt], a[mi],
                                 b4[nt >> 1][(nt & 1) * 2], b4[nt >> 1][(nt & 1) * 2 + 1]);
            }

            // store: even-row warps -> even ring [c&1], odd-row warps -> odd ring [c%3]
            __half* cbase = (wid & 1)
                ? (__half*)(smem + SCO + (size_t)(c % 3) * RBUF)
                : (__half*)(smem + SCE + (size_t)(c & 1) * RBUF);
            const int crow = lane >> 2;
            const int cc2  = (lane & 3) * 2;
#pragma unroll
            for (int mi = 0; mi < 2; ++mi)
#pragma unroll
                for (int nt = 0; nt < 8; ++nt) {
                    const int r0 = mwarp + mi * 16 + crow;
                    const int xx = nt * 8 + cc2;
                    *(__half2*)(cbase + (size_t)r0 * 72 + xx) =
                        __floats2half2_rn(acc[mi][nt][0], acc[mi][nt][1]);
                    *(__half2*)(cbase + (size_t)(r0 + 8) * 72 + xx) =
                        __floats2half2_rn(acc[mi][nt][2], acc[mi][nt][3]);
                }
        }
        __syncthreads();
    }
}

// ---------------------------------------------------------------------------
extern "C" void kernel_launch(void* const* d_in, const int* in_sizes, int n_in,
                              void* d_out, int out_size) {
    const float* fr    = (const float*)d_in[0];
    const float* fs    = (const float*)d_in[1];
    const float* grids = (const float*)d_in[2];
    const float* mask  = (const float*)d_in[3];
    float* out = (float*)d_out;

    cudaFuncSetAttribute(corr_fused_kernel,
                         cudaFuncAttributeMaxDynamicSharedMemorySize, SMEM_TOTAL);

    prelude_kernel<<<6144, 256>>>(fr, fs, grids, mask, out);
    corr_fused_kernel<<<dim3(Q / PT, NB), 512, SMEM_TOTAL>>>(out);
}